// round 6
// baseline (speedup 1.0000x reference)
#include <cuda_runtime.h>
#include <cuda_bf16.h>
#include <math.h>
#include <cstdint>

#define B_SZ   512
#define I_CAPS 1152
#define Q_SZ   8
#define O_CAPS 10
#define P_SZ   16
#define K_TOT  9216          // I*Q
#define N_TOT  160           // O*P
#define NT_N   20            // N_TOT/8
#define KB16_S 576           // K_TOT/16
#define KB16_G 32            // B_SZ/16
#define MT_S   32            // B_SZ/16
#define MT_G   576           // K_TOT/16
#define KSPLIT_S 36          // 16 kb16 per split (256 k)
#define BSPLIT_G 2           // 16 bb16 per split (256 b)

typedef unsigned u32;

// ---------------- static device scratch ----------------
__device__ float g_Wt[K_TOT * N_TOT];                  // [k][n] fp32
__device__ float g_b[I_CAPS * O_CAPS];
__device__ float g_c[I_CAPS * O_CAPS];
__device__ float g_spart[KSPLIT_S][B_SZ * N_TOT];
__device__ float g_v[B_SZ * N_TOT];
__device__ float g_bpart[BSPLIT_G][I_CAPS * O_CAPS];   // fused agreement partials
// A fragments: per (mt,kb): hi uint4 then lo uint4, 32 lanes each
__device__ uint4 g_afs[MT_S * KB16_S * 2 * 32];        // x   18.9 MB
__device__ uint4 g_afg[MT_G * KB16_G * 2 * 32];        // xT  18.9 MB
// B fragments: kb-major: (kb*20 + nt)*32 + lane; uint4 = {bh0,bh1,bl0,bl1}
__device__ uint4 g_bf[KB16_S * NT_N * 32];             // c.W  5.9 MB
__device__ uint4 g_vf[KB16_G * NT_N * 32];             // vT

// ---------------- helpers ----------------
__device__ __forceinline__ void split_pair(float v0, float v1, u32 &hi, u32 &lo) {
    __nv_bfloat16 h0 = __float2bfloat16(v0), h1 = __float2bfloat16(v1);
    __nv_bfloat16 l0 = __float2bfloat16(v0 - __bfloat162float(h0));
    __nv_bfloat16 l1 = __float2bfloat16(v1 - __bfloat162float(h1));
    hi = (u32)__bfloat16_as_ushort(h0) | ((u32)__bfloat16_as_ushort(h1) << 16);
    lo = (u32)__bfloat16_as_ushort(l0) | ((u32)__bfloat16_as_ushort(l1) << 16);
}
__device__ __forceinline__ void mma_bf16(float* d, u32 a0, u32 a1, u32 a2, u32 a3,
                                         u32 b0, u32 b1) {
    asm volatile(
        "mma.sync.aligned.m16n8k16.row.col.f32.bf16.bf16.f32 "
        "{%0,%1,%2,%3}, {%4,%5,%6,%7}, {%8,%9}, {%0,%1,%2,%3};"
        : "+f"(d[0]), "+f"(d[1]), "+f"(d[2]), "+f"(d[3])
        : "r"(a0), "r"(a1), "r"(a2), "r"(a3), "r"(b0), "r"(b1));
}

// ---------------- prep: Wt fp32 [k][n]; zero b ----------------
__global__ void wt_kernel(const float* __restrict__ W) {
    int t = blockIdx.x * 256 + threadIdx.x;
    if (t < I_CAPS * O_CAPS) g_b[t] = 0.0f;
    if (t >= K_TOT * N_TOT) return;
    int k = t / N_TOT, n = t - k * N_TOT;
    int i = k >> 3, q = k & 7, o = n >> 4, p = n & 15;
    g_Wt[t] = W[(i * O_CAPS + o) * (P_SZ * Q_SZ) + p * Q_SZ + q];
}

// ---------------- one-time: x -> A fragments (s and G) ----------------
__global__ void xprep_kernel(const float* __restrict__ x) {
    __shared__ float st[16][129];
    const int bx = blockIdx.x, by = blockIdx.y;
    const int k0 = bx * 128, b0 = by * 16;
    const int t = threadIdx.x, w = t >> 5, l = t & 31;
    const int gid = l >> 2, tid = l & 3;

    #pragma unroll
    for (int j = 0; j < 2; j++) {
        int f = t + 256 * j;
        int row = f >> 5, c4 = f & 31;
        float4 v = *(const float4*)&x[(size_t)(b0 + row) * K_TOT + k0 + c4 * 4];
        st[row][c4 * 4 + 0] = v.x; st[row][c4 * 4 + 1] = v.y;
        st[row][c4 * 4 + 2] = v.z; st[row][c4 * 4 + 3] = v.w;
    }
    __syncthreads();

    const int j16 = w * 16;
    {   // s fragment: (mt = by, kb = bx*8 + w)
        uint4 hi, lo;
        split_pair(st[gid][j16 + 2 * tid],     st[gid][j16 + 2 * tid + 1],     hi.x, lo.x);
        split_pair(st[gid + 8][j16 + 2 * tid], st[gid + 8][j16 + 2 * tid + 1], hi.y, lo.y);
        split_pair(st[gid][j16 + 2 * tid + 8], st[gid][j16 + 2 * tid + 9],     hi.z, lo.z);
        split_pair(st[gid + 8][j16 + 2 * tid + 8], st[gid + 8][j16 + 2 * tid + 9], hi.w, lo.w);
        size_t base = (((size_t)by * KB16_S + bx * 8 + w) * 2) * 32 + l;
        g_afs[base] = hi;
        g_afs[base + 32] = lo;
    }
    {   // G fragment: (mt = bx*8 + w, bb = by)
        uint4 hi, lo;
        split_pair(st[2 * tid][j16 + gid],         st[2 * tid + 1][j16 + gid],     hi.x, lo.x);
        split_pair(st[2 * tid][j16 + gid + 8],     st[2 * tid + 1][j16 + gid + 8], hi.y, lo.y);
        split_pair(st[2 * tid + 8][j16 + gid],     st[2 * tid + 9][j16 + gid],     hi.z, lo.z);
        split_pair(st[2 * tid + 8][j16 + gid + 8], st[2 * tid + 9][j16 + gid + 8], hi.w, lo.w);
        size_t base = (((size_t)(bx * 8 + w) * KB16_G + by) * 2) * 32 + l;
        g_afg[base] = hi;
        g_afg[base + 32] = lo;
    }
}

// ---------------- softmax (+ optional bpart accumulation) ----------------
__global__ void __launch_bounds__(1024) softmax_kernel(int add_parts) {
    int t = threadIdx.x;
    if (add_parts) {
        for (int idx = t; idx < I_CAPS * O_CAPS; idx += 1024)
            g_b[idx] += (g_bpart[0][idx] + g_bpart[1][idx]) * (1.0f / (float)B_SZ);
        __syncthreads();
    }
    int w = t >> 5, lane = t & 31;
    if (w >= O_CAPS) return;
    int o = w;
    float mx = -1e30f;
    for (int i = lane; i < I_CAPS; i += 32) mx = fmaxf(mx, g_b[i * O_CAPS + o]);
    #pragma unroll
    for (int off = 16; off; off >>= 1) mx = fmaxf(mx, __shfl_xor_sync(~0u, mx, off));
    float sum = 0.0f;
    for (int i = lane; i < I_CAPS; i += 32) sum += expf(g_b[i * O_CAPS + o] - mx);
    #pragma unroll
    for (int off = 16; off; off >>= 1) sum += __shfl_xor_sync(~0u, sum, off);
    float inv = 1.0f / sum;
    for (int i = lane; i < I_CAPS; i += 32)
        g_c[i * O_CAPS + o] = expf(g_b[i * O_CAPS + o] - mx) * inv;
}

// ---------------- per-iter: B fragments of (c .* W) ----------------
__global__ void bfrag_kernel(const float* __restrict__ W) {
    int wg = blockIdx.x * 8 + (threadIdx.x >> 5);     // kb*20 + nt
    int l = threadIdx.x & 31;
    int kb = wg / NT_N, nt = wg - kb * NT_N;
    int gid = l >> 2, tid = l & 3;
    int n = nt * 8 + gid, o = n >> 4, p = n & 15;
    int i0 = kb * 2, i1 = kb * 2 + 1;
    float c0 = g_c[i0 * O_CAPS + o], c1 = g_c[i1 * O_CAPS + o];
    const float* w0 = &W[((i0 * O_CAPS + o) * P_SZ + p) * Q_SZ];
    const float* w1 = &W[((i1 * O_CAPS + o) * P_SZ + p) * Q_SZ];
    uint4 r;
    split_pair(c0 * w0[2 * tid], c0 * w0[2 * tid + 1], r.x, r.z);
    split_pair(c1 * w1[2 * tid], c1 * w1[2 * tid + 1], r.y, r.w);
    g_bf[(size_t)wg * 32 + l] = r;
}

// ---------------- per-iter: B fragments of vT ----------------
__global__ void vfrag_kernel() {
    int wg = blockIdx.x * 8 + (threadIdx.x >> 5);     // bb*20 + nt, < 640
    int l = threadIdx.x & 31;
    int bb = wg / NT_N, nt = wg - bb * NT_N;
    int gid = l >> 2, tid = l & 3;
    int n = nt * 8 + gid;
    int b0 = bb * 16 + 2 * tid;
    uint4 r;
    split_pair(g_v[b0 * N_TOT + n],       g_v[(b0 + 1) * N_TOT + n], r.x, r.z);
    split_pair(g_v[(b0 + 8) * N_TOT + n], g_v[(b0 + 9) * N_TOT + n], r.y, r.w);
    g_vf[(size_t)wg * 32 + l] = r;
}

// ---------------- s-GEMM: split-bf16, grid (4, 36), 16 kb16 per split ----------------
__global__ void __launch_bounds__(128) s_gemm_kernel() {
    const int t = threadIdx.x, w = t >> 5, l = t & 31;
    const int gid = l >> 2, tid = l & 3;
    const int mtbase = blockIdx.x * 8 + w * 2;
    const int kb0 = blockIdx.y * 16;
    float* out = &g_spart[blockIdx.y][0];

    float d[2][NT_N][4];
    #pragma unroll
    for (int a = 0; a < 2; a++)
        #pragma unroll
        for (int nt = 0; nt < NT_N; nt++)
            #pragma unroll
            for (int e = 0; e < 4; e++) d[a][nt][e] = 0.0f;

    #pragma unroll 1
    for (int kb = 0; kb < 16; ++kb) {
        size_t a0base = (((size_t)(mtbase + 0) * KB16_S + kb0 + kb) * 2) * 32 + l;
        size_t a1base = (((size_t)(mtbase + 1) * KB16_S + kb0 + kb) * 2) * 32 + l;
        uint4 a0h = g_afs[a0base], a0l = g_afs[a0base + 32];
        uint4 a1h = g_afs[a1base], a1l = g_afs[a1base + 32];
        const uint4* Bk = &g_bf[(size_t)(kb0 + kb) * NT_N * 32 + l];
        #pragma unroll
        for (int nt = 0; nt < NT_N; nt++) {
            uint4 b = Bk[nt * 32];
            mma_bf16(d[0][nt], a0h.x, a0h.y, a0h.z, a0h.w, b.x, b.y);
            mma_bf16(d[0][nt], a0h.x, a0h.y, a0h.z, a0h.w, b.z, b.w);
            mma_bf16(d[0][nt], a0l.x, a0l.y, a0l.z, a0l.w, b.x, b.y);
            mma_bf16(d[1][nt], a1h.x, a1h.y, a1h.z, a1h.w, b.x, b.y);
            mma_bf16(d[1][nt], a1h.x, a1h.y, a1h.z, a1h.w, b.z, b.w);
            mma_bf16(d[1][nt], a1l.x, a1l.y, a1l.z, a1l.w, b.x, b.y);
        }
    }

    #pragma unroll
    for (int a = 0; a < 2; a++) {
        int m = (mtbase + a) * 16 + gid;
        #pragma unroll
        for (int nt = 0; nt < NT_N; nt++) {
            int col = nt * 8 + tid * 2;
            *(float2*)&out[(size_t)m * N_TOT + col] = make_float2(d[a][nt][0], d[a][nt][1]);
            *(float2*)&out[(size_t)(m + 8) * N_TOT + col] = make_float2(d[a][nt][2], d[a][nt][3]);
        }
    }
}

// ---------------- G-GEMM with fused agreement dot, grid (72, 2) ----------------
// Computes G tile in registers, immediately contracts with Wt into (i,o) partials.
__global__ void __launch_bounds__(128) g_gemm_kernel() {
    const int t = threadIdx.x, w = t >> 5, l = t & 31;
    const int gid = l >> 2, tid = l & 3;
    const int mtbase = blockIdx.x * 8 + w * 2;
    const int bb0 = blockIdx.y * 16;

    float d[2][NT_N][4];
    #pragma unroll
    for (int a = 0; a < 2; a++)
        #pragma unroll
        for (int nt = 0; nt < NT_N; nt++)
            #pragma unroll
            for (int e = 0; e < 4; e++) d[a][nt][e] = 0.0f;

    #pragma unroll 1
    for (int bb = 0; bb < 16; ++bb) {
        size_t a0base = (((size_t)(mtbase + 0) * KB16_G + bb0 + bb) * 2) * 32 + l;
        size_t a1base = (((size_t)(mtbase + 1) * KB16_G + bb0 + bb) * 2) * 32 + l;
        uint4 a0h = g_afg[a0base], a0l = g_afg[a0base + 32];
        uint4 a1h = g_afg[a1base], a1l = g_afg[a1base + 32];
        const uint4* Bk = &g_vf[(size_t)(bb0 + bb) * NT_N * 32 + l];
        #pragma unroll
        for (int nt = 0; nt < NT_N; nt++) {
            uint4 b = Bk[nt * 32];
            mma_bf16(d[0][nt], a0h.x, a0h.y, a0h.z, a0h.w, b.x, b.y);
            mma_bf16(d[0][nt], a0h.x, a0h.y, a0h.z, a0h.w, b.z, b.w);
            mma_bf16(d[0][nt], a0l.x, a0l.y, a0l.z, a0l.w, b.x, b.y);
            mma_bf16(d[1][nt], a1h.x, a1h.y, a1h.z, a1h.w, b.x, b.y);
            mma_bf16(d[1][nt], a1h.x, a1h.y, a1h.z, a1h.w, b.z, b.w);
            mma_bf16(d[1][nt], a1l.x, a1l.y, a1l.z, a1l.w, b.x, b.y);
        }
    }

    // fused epilogue: contract G fragment with Wt into (i,o) partials.
    // rows: m = (mtbase+a)*16 + gid + 8h  -> i = 2*(mtbase+a)+h, q = gid
    #pragma unroll
    for (int a = 0; a < 2; a++) {
        #pragma unroll
        for (int h = 0; h < 2; h++) {
            int row = (mtbase + a) * 16 + gid + 8 * h;
            int iidx = 2 * (mtbase + a) + h;
            #pragma unroll
            for (int o = 0; o < O_CAPS; o++) {
                float2 w0 = *(const float2*)&g_Wt[(size_t)row * N_TOT + (2 * o) * 8 + tid * 2];
                float2 w1 = *(const float2*)&g_Wt[(size_t)row * N_TOT + (2 * o + 1) * 8 + tid * 2];
                float p = d[a][2 * o][2 * h] * w0.x + d[a][2 * o][2 * h + 1] * w0.y
                        + d[a][2 * o + 1][2 * h] * w1.x + d[a][2 * o + 1][2 * h + 1] * w1.y;
                #pragma unroll
                for (int off = 16; off; off >>= 1)
                    p += __shfl_xor_sync(~0u, p, off);
                if (l == o)
                    g_bpart[blockIdx.y][iidx * O_CAPS + o] = p;
            }
        }
    }
}

// ---------------- reduce split-K + squash ----------------
__global__ void squash_kernel(float* __restrict__ out, int write_out) {
    int tid = blockIdx.x * 256 + threadIdx.x;   // < 81920
    float sv = 0.0f;
    #pragma unroll 6
    for (int sp = 0; sp < KSPLIT_S; ++sp) sv += g_spart[sp][tid];
    float sq = sv * sv;
    #pragma unroll
    for (int off = 8; off; off >>= 1) sq += __shfl_xor_sync(~0u, sq, off);
    float norm = sqrtf(sq + 1e-8f);
    float vv = (sq / (1.0f + sq)) * (sv / norm);
    g_v[tid] = vv;
    if (write_out) out[tid] = vv;
}

// ---------------- launch ----------------
extern "C" void kernel_launch(void* const* d_in, const int* in_sizes, int n_in,
                              void* d_out, int out_size) {
    const float* x = (const float*)d_in[0];
    const float* W = (const float*)d_in[1];
    if (n_in >= 2 && in_sizes[0] == I_CAPS * O_CAPS * P_SZ * Q_SZ) {
        W = (const float*)d_in[0];
        x = (const float*)d_in[1];
    }
    float* out = (float*)d_out;

    wt_kernel<<<(K_TOT * N_TOT + 255) / 256, 256>>>(W);
    xprep_kernel<<<dim3(K_TOT / 128, B_SZ / 16), 256>>>(x);

    for (int it = 0; it < 3; ++it) {
        softmax_kernel<<<1, 1024>>>(it > 0 ? 1 : 0);
        bfrag_kernel<<<(KB16_S * NT_N) / 8, 256>>>(W);
        s_gemm_kernel<<<dim3(MT_S / 8, KSPLIT_S), 128>>>();
        squash_kernel<<<(B_SZ * N_TOT) / 256, 256>>>(out, it == 2 ? 1 : 0);
        if (it < 2) {
            vfrag_kernel<<<(KB16_G * NT_N) / 8, 256>>>();
            g_gemm_kernel<<<dim3(MT_G / 8, BSPLIT_G), 128>>>();
        }
    }
}

// round 7
// speedup vs baseline: 1.1420x; 1.1420x over previous
#include <cuda_runtime.h>
#include <cuda_bf16.h>
#include <math.h>
#include <cstdint>

#define B_SZ   512
#define I_CAPS 1152
#define Q_SZ   8
#define O_CAPS 10
#define P_SZ   16
#define K_TOT  9216          // I*Q
#define N_TOT  160           // O*P
#define NT_N   20            // N_TOT/8
#define KB16_S 576           // K_TOT/16
#define KB16_G 32            // B_SZ/16
#define MT_S   32            // B_SZ/16
#define MT_G   576           // K_TOT/16
#define KSPLIT_S 72          // 8 kb16 per split (128 k)
#define BSPLIT_G 4           // 8 bb16 per split (128 b)

typedef unsigned u32;

// ---------------- static device scratch ----------------
__device__ float g_Wt[K_TOT * N_TOT];                  // [k][n] fp32
__device__ float g_b[I_CAPS * O_CAPS];
__device__ float g_c[I_CAPS * O_CAPS];
__device__ float g_spart[KSPLIT_S][B_SZ * N_TOT];
__device__ float g_v[B_SZ * N_TOT];
__device__ float g_bpart[BSPLIT_G][I_CAPS * O_CAPS];   // fused agreement partials
// A fragments: per (mt,kb): hi uint4 then lo uint4, 32 lanes each
__device__ uint4 g_afs[MT_S * KB16_S * 2 * 32];        // x   18.9 MB
__device__ uint4 g_afg[MT_G * KB16_G * 2 * 32];        // xT  18.9 MB
// B fragments: kb-major: (kb*20 + nt)*32 + lane; uint4 = {bh0,bh1,bl0,bl1}
__device__ uint4 g_bf[KB16_S * NT_N * 32];             // c.W  5.9 MB
__device__ uint4 g_vf[KB16_G * NT_N * 32];             // vT

// ---------------- helpers ----------------
__device__ __forceinline__ void split_pair(float v0, float v1, u32 &hi, u32 &lo) {
    __nv_bfloat16 h0 = __float2bfloat16(v0), h1 = __float2bfloat16(v1);
    __nv_bfloat16 l0 = __float2bfloat16(v0 - __bfloat162float(h0));
    __nv_bfloat16 l1 = __float2bfloat16(v1 - __bfloat162float(h1));
    hi = (u32)__bfloat16_as_ushort(h0) | ((u32)__bfloat16_as_ushort(h1) << 16);
    lo = (u32)__bfloat16_as_ushort(l0) | ((u32)__bfloat16_as_ushort(l1) << 16);
}
__device__ __forceinline__ void mma_bf16(float* d, u32 a0, u32 a1, u32 a2, u32 a3,
                                         u32 b0, u32 b1) {
    asm volatile(
        "mma.sync.aligned.m16n8k16.row.col.f32.bf16.bf16.f32 "
        "{%0,%1,%2,%3}, {%4,%5,%6,%7}, {%8,%9}, {%0,%1,%2,%3};"
        : "+f"(d[0]), "+f"(d[1]), "+f"(d[2]), "+f"(d[3])
        : "r"(a0), "r"(a1), "r"(a2), "r"(a3), "r"(b0), "r"(b1));
}

// ---------------- prep: Wt fp32 [k][n]; zero b; c = uniform (it-0 softmax) ----------------
__global__ void wt_kernel(const float* __restrict__ W) {
    int t = blockIdx.x * 256 + threadIdx.x;
    if (t < I_CAPS * O_CAPS) {
        g_b[t] = 0.0f;
        g_c[t] = 1.0f / (float)I_CAPS;
    }
    if (t >= K_TOT * N_TOT) return;
    int k = t / N_TOT, n = t - k * N_TOT;
    int i = k >> 3, q = k & 7, o = n >> 4, p = n & 15;
    g_Wt[t] = W[(i * O_CAPS + o) * (P_SZ * Q_SZ) + p * Q_SZ + q];
}

// ---------------- one-time: x -> A fragments (s and G) ----------------
__global__ void xprep_kernel(const float* __restrict__ x) {
    __shared__ float st[16][129];
    const int bx = blockIdx.x, by = blockIdx.y;
    const int k0 = bx * 128, b0 = by * 16;
    const int t = threadIdx.x, w = t >> 5, l = t & 31;
    const int gid = l >> 2, tid = l & 3;

    #pragma unroll
    for (int j = 0; j < 2; j++) {
        int f = t + 256 * j;
        int row = f >> 5, c4 = f & 31;
        float4 v = *(const float4*)&x[(size_t)(b0 + row) * K_TOT + k0 + c4 * 4];
        st[row][c4 * 4 + 0] = v.x; st[row][c4 * 4 + 1] = v.y;
        st[row][c4 * 4 + 2] = v.z; st[row][c4 * 4 + 3] = v.w;
    }
    __syncthreads();

    const int j16 = w * 16;
    {   // s fragment: (mt = by, kb = bx*8 + w)
        uint4 hi, lo;
        split_pair(st[gid][j16 + 2 * tid],     st[gid][j16 + 2 * tid + 1],     hi.x, lo.x);
        split_pair(st[gid + 8][j16 + 2 * tid], st[gid + 8][j16 + 2 * tid + 1], hi.y, lo.y);
        split_pair(st[gid][j16 + 2 * tid + 8], st[gid][j16 + 2 * tid + 9],     hi.z, lo.z);
        split_pair(st[gid + 8][j16 + 2 * tid + 8], st[gid + 8][j16 + 2 * tid + 9], hi.w, lo.w);
        size_t base = (((size_t)by * KB16_S + bx * 8 + w) * 2) * 32 + l;
        g_afs[base] = hi;
        g_afs[base + 32] = lo;
    }
    {   // G fragment: (mt = bx*8 + w, bb = by)
        uint4 hi, lo;
        split_pair(st[2 * tid][j16 + gid],         st[2 * tid + 1][j16 + gid],     hi.x, lo.x);
        split_pair(st[2 * tid][j16 + gid + 8],     st[2 * tid + 1][j16 + gid + 8], hi.y, lo.y);
        split_pair(st[2 * tid + 8][j16 + gid],     st[2 * tid + 9][j16 + gid],     hi.z, lo.z);
        split_pair(st[2 * tid + 8][j16 + gid + 8], st[2 * tid + 9][j16 + gid + 8], hi.w, lo.w);
        size_t base = (((size_t)(bx * 8 + w) * KB16_G + by) * 2) * 32 + l;
        g_afg[base] = hi;
        g_afg[base + 32] = lo;
    }
}

// ---------------- softmax with bpart accumulation (iters 1,2 only) ----------------
__global__ void __launch_bounds__(1024) softmax_kernel() {
    int t = threadIdx.x;
    for (int idx = t; idx < I_CAPS * O_CAPS; idx += 1024)
        g_b[idx] += (g_bpart[0][idx] + g_bpart[1][idx] + g_bpart[2][idx] + g_bpart[3][idx])
                    * (1.0f / (float)B_SZ);
    __syncthreads();
    int w = t >> 5, lane = t & 31;
    if (w >= O_CAPS) return;
    int o = w;
    float mx = -1e30f;
    for (int i = lane; i < I_CAPS; i += 32) mx = fmaxf(mx, g_b[i * O_CAPS + o]);
    #pragma unroll
    for (int off = 16; off; off >>= 1) mx = fmaxf(mx, __shfl_xor_sync(~0u, mx, off));
    float sum = 0.0f;
    for (int i = lane; i < I_CAPS; i += 32) sum += expf(g_b[i * O_CAPS + o] - mx);
    #pragma unroll
    for (int off = 16; off; off >>= 1) sum += __shfl_xor_sync(~0u, sum, off);
    float inv = 1.0f / sum;
    for (int i = lane; i < I_CAPS; i += 32)
        g_c[i * O_CAPS + o] = expf(g_b[i * O_CAPS + o] - mx) * inv;
}

// ---------------- per-iter: B fragments of (c .* W) ----------------
__global__ void bfrag_kernel(const float* __restrict__ W) {
    int wg = blockIdx.x * 8 + (threadIdx.x >> 5);     // kb*20 + nt
    int l = threadIdx.x & 31;
    int kb = wg / NT_N, nt = wg - kb * NT_N;
    int gid = l >> 2, tid = l & 3;
    int n = nt * 8 + gid, o = n >> 4, p = n & 15;
    int i0 = kb * 2, i1 = kb * 2 + 1;
    float c0 = g_c[i0 * O_CAPS + o], c1 = g_c[i1 * O_CAPS + o];
    const float* w0 = &W[((i0 * O_CAPS + o) * P_SZ + p) * Q_SZ];
    const float* w1 = &W[((i1 * O_CAPS + o) * P_SZ + p) * Q_SZ];
    uint4 r;
    split_pair(c0 * w0[2 * tid], c0 * w0[2 * tid + 1], r.x, r.z);
    split_pair(c1 * w1[2 * tid], c1 * w1[2 * tid + 1], r.y, r.w);
    g_bf[(size_t)wg * 32 + l] = r;
}

// ---------------- per-iter: B fragments of vT ----------------
__global__ void vfrag_kernel() {
    int wg = blockIdx.x * 8 + (threadIdx.x >> 5);     // bb*20 + nt, < 640
    int l = threadIdx.x & 31;
    int bb = wg / NT_N, nt = wg - bb * NT_N;
    int gid = l >> 2, tid = l & 3;
    int n = nt * 8 + gid;
    int b0 = bb * 16 + 2 * tid;
    uint4 r;
    split_pair(g_v[b0 * N_TOT + n],       g_v[(b0 + 1) * N_TOT + n], r.x, r.z);
    split_pair(g_v[(b0 + 8) * N_TOT + n], g_v[(b0 + 9) * N_TOT + n], r.y, r.w);
    g_vf[(size_t)wg * 32 + l] = r;
}

// ---------------- s-GEMM: split-bf16, grid (4, 72), 8 kb16 per split ----------------
__global__ void __launch_bounds__(128) s_gemm_kernel() {
    const int t = threadIdx.x, w = t >> 5, l = t & 31;
    const int gid = l >> 2, tid = l & 3;
    const int mtbase = blockIdx.x * 8 + w * 2;
    const int kb0 = blockIdx.y * 8;
    float* out = &g_spart[blockIdx.y][0];

    float d[2][NT_N][4];
    #pragma unroll
    for (int a = 0; a < 2; a++)
        #pragma unroll
        for (int nt = 0; nt < NT_N; nt++)
            #pragma unroll
            for (int e = 0; e < 4; e++) d[a][nt][e] = 0.0f;

    #pragma unroll 1
    for (int kb = 0; kb < 8; ++kb) {
        size_t a0base = (((size_t)(mtbase + 0) * KB16_S + kb0 + kb) * 2) * 32 + l;
        size_t a1base = (((size_t)(mtbase + 1) * KB16_S + kb0 + kb) * 2) * 32 + l;
        uint4 a0h = g_afs[a0base], a0l = g_afs[a0base + 32];
        uint4 a1h = g_afs[a1base], a1l = g_afs[a1base + 32];
        const uint4* Bk = &g_bf[(size_t)(kb0 + kb) * NT_N * 32 + l];
        #pragma unroll
        for (int nt = 0; nt < NT_N; nt++) {
            uint4 b = Bk[nt * 32];
            mma_bf16(d[0][nt], a0h.x, a0h.y, a0h.z, a0h.w, b.x, b.y);
            mma_bf16(d[0][nt], a0h.x, a0h.y, a0h.z, a0h.w, b.z, b.w);
            mma_bf16(d[0][nt], a0l.x, a0l.y, a0l.z, a0l.w, b.x, b.y);
            mma_bf16(d[1][nt], a1h.x, a1h.y, a1h.z, a1h.w, b.x, b.y);
            mma_bf16(d[1][nt], a1h.x, a1h.y, a1h.z, a1h.w, b.z, b.w);
            mma_bf16(d[1][nt], a1l.x, a1l.y, a1l.z, a1l.w, b.x, b.y);
        }
    }

    #pragma unroll
    for (int a = 0; a < 2; a++) {
        int m = (mtbase + a) * 16 + gid;
        #pragma unroll
        for (int nt = 0; nt < NT_N; nt++) {
            int col = nt * 8 + tid * 2;
            *(float2*)&out[(size_t)m * N_TOT + col] = make_float2(d[a][nt][0], d[a][nt][1]);
            *(float2*)&out[(size_t)(m + 8) * N_TOT + col] = make_float2(d[a][nt][2], d[a][nt][3]);
        }
    }
}

// ---------------- G-GEMM, grid (72, 4), 8 bb16 per split; fused agreement epilogue ----
__global__ void __launch_bounds__(128) g_gemm_kernel() {
    const int t = threadIdx.x, w = t >> 5, l = t & 31;
    const int gid = l >> 2, tid = l & 3;
    const int mtbase = blockIdx.x * 8 + w * 2;
    const int bb0 = blockIdx.y * 8;

    float d[2][NT_N][4];
    #pragma unroll
    for (int a = 0; a < 2; a++)
        #pragma unroll
        for (int nt = 0; nt < NT_N; nt++)
            #pragma unroll
            for (int e = 0; e < 4; e++) d[a][nt][e] = 0.0f;

    #pragma unroll 1
    for (int bb = 0; bb < 8; ++bb) {
        size_t a0base = (((size_t)(mtbase + 0) * KB16_G + bb0 + bb) * 2) * 32 + l;
        size_t a1base = (((size_t)(mtbase + 1) * KB16_G + bb0 + bb) * 2) * 32 + l;
        uint4 a0h = g_afg[a0base], a0l = g_afg[a0base + 32];
        uint4 a1h = g_afg[a1base], a1l = g_afg[a1base + 32];
        const uint4* Bk = &g_vf[(size_t)(bb0 + bb) * NT_N * 32 + l];
        #pragma unroll
        for (int nt = 0; nt < NT_N; nt++) {
            uint4 b = Bk[nt * 32];
            mma_bf16(d[0][nt], a0h.x, a0h.y, a0h.z, a0h.w, b.x, b.y);
            mma_bf16(d[0][nt], a0h.x, a0h.y, a0h.z, a0h.w, b.z, b.w);
            mma_bf16(d[0][nt], a0l.x, a0l.y, a0l.z, a0l.w, b.x, b.y);
            mma_bf16(d[1][nt], a1h.x, a1h.y, a1h.z, a1h.w, b.x, b.y);
            mma_bf16(d[1][nt], a1h.x, a1h.y, a1h.z, a1h.w, b.z, b.w);
            mma_bf16(d[1][nt], a1l.x, a1l.y, a1l.z, a1l.w, b.x, b.y);
        }
    }

    // fused epilogue: contract G fragment with Wt -> (i,o) partials; no Gpart.
    // d[a][nt][2h+c] = G[(mtbase+a)*16 + gid + 8h, nt*8 + tid*2 + c]; i = 2(mtbase+a)+h, q = gid.
    #pragma unroll
    for (int a = 0; a < 2; a++) {
        #pragma unroll
        for (int h = 0; h < 2; h++) {
            int row = (mtbase + a) * 16 + gid + 8 * h;
            int iidx = 2 * (mtbase + a) + h;
            #pragma unroll
            for (int o = 0; o < O_CAPS; o++) {
                float2 w0 = *(const float2*)&g_Wt[(size_t)row * N_TOT + o * 16 + tid * 2];
                float2 w1 = *(const float2*)&g_Wt[(size_t)row * N_TOT + o * 16 + 8 + tid * 2];
                float p = d[a][2 * o][2 * h] * w0.x + d[a][2 * o][2 * h + 1] * w0.y
                        + d[a][2 * o + 1][2 * h] * w1.x + d[a][2 * o + 1][2 * h + 1] * w1.y;
                #pragma unroll
                for (int off = 16; off; off >>= 1)
                    p += __shfl_xor_sync(~0u, p, off);
                if (l == o)
                    g_bpart[blockIdx.y][iidx * O_CAPS + o] = p;
            }
        }
    }
}

// ---------------- reduce split-K + squash (float2 vectorized) ----------------
__global__ void squash_kernel(float* __restrict__ out, int write_out) {
    int idx = blockIdx.x * 256 + threadIdx.x;   // pair index < 40960
    int base = idx * 2;
    float2 sv = make_float2(0.0f, 0.0f);
    #pragma unroll 8
    for (int sp = 0; sp < KSPLIT_S; ++sp) {
        float2 p = *(const float2*)&g_spart[sp][base];
        sv.x += p.x; sv.y += p.y;
    }
    float sq = sv.x * sv.x + sv.y * sv.y;
    #pragma unroll
    for (int off = 4; off; off >>= 1)
        sq += __shfl_xor_sync(~0u, sq, off);   // reduce over 8-lane p-group
    float norm = sqrtf(sq + 1e-8f);
    float sc = (sq / (1.0f + sq)) / norm;
    float2 vv = make_float2(sv.x * sc, sv.y * sc);
    *(float2*)&g_v[base] = vv;
    if (write_out) *(float2*)&out[base] = vv;
}

// ---------------- launch ----------------
extern "C" void kernel_launch(void* const* d_in, const int* in_sizes, int n_in,
                              void* d_out, int out_size) {
    const float* x = (const float*)d_in[0];
    const float* W = (const float*)d_in[1];
    if (n_in >= 2 && in_sizes[0] == I_CAPS * O_CAPS * P_SZ * Q_SZ) {
        W = (const float*)d_in[0];
        x = (const float*)d_in[1];
    }
    float* out = (float*)d_out;

    wt_kernel<<<(K_TOT * N_TOT + 255) / 256, 256>>>(W);      // also sets c uniform
    xprep_kernel<<<dim3(K_TOT / 128, B_SZ / 16), 256>>>(x);

    for (int it = 0; it < 3; ++it) {
        if (it > 0) softmax_kernel<<<1, 1024>>>();
        bfrag_kernel<<<(KB16_S * NT_N) / 8, 256>>>(W);
        s_gemm_kernel<<<dim3(MT_S / 8, KSPLIT_S), 128>>>();
        squash_kernel<<<(B_SZ * N_TOT / 2) / 256, 256>>>(out, it == 2 ? 1 : 0);
        if (it < 2) {
            vfrag_kernel<<<(KB16_G * NT_N) / 8, 256>>>();
            g_gemm_kernel<<<dim3(MT_G / 8, BSPLIT_G), 128>>>();
        }
    }
}

// round 8
// speedup vs baseline: 1.2481x; 1.0929x over previous
#include <cuda_runtime.h>
#include <cuda_bf16.h>
#include <math.h>
#include <cstdint>

#define B_SZ   512
#define I_CAPS 1152
#define Q_SZ   8
#define O_CAPS 10
#define P_SZ   16
#define K_TOT  9216          // I*Q
#define N_TOT  160           // O*P
#define NT_N   20            // N_TOT/8
#define NT_H   10            // nt per CTA (N-split)
#define KB16_S 576           // K_TOT/16
#define KB16_G 32            // B_SZ/16
#define MT_S   32            // B_SZ/16
#define MT_G   576           // K_TOT/16
#define KSPLIT_S 72          // 8 kb16 per split (128 k)
#define BSPLIT_G 4           // 8 bb16 per split (128 b)

typedef unsigned u32;

// ---------------- static device scratch ----------------
__device__ float g_Wt[K_TOT * N_TOT];                  // [k][n] fp32
__device__ float g_b[I_CAPS * O_CAPS];
__device__ float g_c[I_CAPS * O_CAPS];
__device__ float g_spart[KSPLIT_S][B_SZ * N_TOT];
__device__ float g_v[B_SZ * N_TOT];
__device__ float g_Gpart[BSPLIT_G][K_TOT * N_TOT];
// A fragments: per (mt,kb): hi uint4 then lo uint4, 32 lanes each
__device__ uint4 g_afs[MT_S * KB16_S * 2 * 32];        // x   18.9 MB
__device__ uint4 g_afg[MT_G * KB16_G * 2 * 32];        // xT  18.9 MB
// B fragments: kb-major: (kb*20 + nt)*32 + lane; uint4 = {bh0,bh1,bl0,bl1}
__device__ uint4 g_bf[KB16_S * NT_N * 32];             // c.W  5.9 MB
__device__ uint4 g_vf[KB16_G * NT_N * 32];             // vT

// ---------------- helpers ----------------
__device__ __forceinline__ void split_pair(float v0, float v1, u32 &hi, u32 &lo) {
    __nv_bfloat16 h0 = __float2bfloat16(v0), h1 = __float2bfloat16(v1);
    __nv_bfloat16 l0 = __float2bfloat16(v0 - __bfloat162float(h0));
    __nv_bfloat16 l1 = __float2bfloat16(v1 - __bfloat162float(h1));
    hi = (u32)__bfloat16_as_ushort(h0) | ((u32)__bfloat16_as_ushort(h1) << 16);
    lo = (u32)__bfloat16_as_ushort(l0) | ((u32)__bfloat16_as_ushort(l1) << 16);
}
__device__ __forceinline__ void mma_bf16(float* d, u32 a0, u32 a1, u32 a2, u32 a3,
                                         u32 b0, u32 b1) {
    asm volatile(
        "mma.sync.aligned.m16n8k16.row.col.f32.bf16.bf16.f32 "
        "{%0,%1,%2,%3}, {%4,%5,%6,%7}, {%8,%9}, {%0,%1,%2,%3};"
        : "+f"(d[0]), "+f"(d[1]), "+f"(d[2]), "+f"(d[3])
        : "r"(a0), "r"(a1), "r"(a2), "r"(a3), "r"(b0), "r"(b1));
}

// ---------------- prep: Wt fp32 [k][n]; zero b; uniform c (iter-0 softmax) ----------------
__global__ void wt_kernel(const float* __restrict__ W) {
    int t = blockIdx.x * 256 + threadIdx.x;
    if (t < I_CAPS * O_CAPS) {
        g_b[t] = 0.0f;
        g_c[t] = 1.0f / (float)I_CAPS;
    }
    if (t >= K_TOT * N_TOT) return;
    int k = t / N_TOT, n = t - k * N_TOT;
    int i = k >> 3, q = k & 7, o = n >> 4, p = n & 15;
    g_Wt[t] = W[(i * O_CAPS + o) * (P_SZ * Q_SZ) + p * Q_SZ + q];
}

// ---------------- one-time: x -> A fragments (s and G) ----------------
__global__ void xprep_kernel(const float* __restrict__ x) {
    __shared__ float st[16][129];
    const int bx = blockIdx.x, by = blockIdx.y;
    const int k0 = bx * 128, b0 = by * 16;
    const int t = threadIdx.x, w = t >> 5, l = t & 31;
    const int gid = l >> 2, tid = l & 3;

    #pragma unroll
    for (int j = 0; j < 2; j++) {
        int f = t + 256 * j;
        int row = f >> 5, c4 = f & 31;
        float4 v = *(const float4*)&x[(size_t)(b0 + row) * K_TOT + k0 + c4 * 4];
        st[row][c4 * 4 + 0] = v.x; st[row][c4 * 4 + 1] = v.y;
        st[row][c4 * 4 + 2] = v.z; st[row][c4 * 4 + 3] = v.w;
    }
    __syncthreads();

    const int j16 = w * 16;
    {   // s fragment: (mt = by, kb = bx*8 + w)
        uint4 hi, lo;
        split_pair(st[gid][j16 + 2 * tid],     st[gid][j16 + 2 * tid + 1],     hi.x, lo.x);
        split_pair(st[gid + 8][j16 + 2 * tid], st[gid + 8][j16 + 2 * tid + 1], hi.y, lo.y);
        split_pair(st[gid][j16 + 2 * tid + 8], st[gid][j16 + 2 * tid + 9],     hi.z, lo.z);
        split_pair(st[gid + 8][j16 + 2 * tid + 8], st[gid + 8][j16 + 2 * tid + 9], hi.w, lo.w);
        size_t base = (((size_t)by * KB16_S + bx * 8 + w) * 2) * 32 + l;
        g_afs[base] = hi;
        g_afs[base + 32] = lo;
    }
    {   // G fragment: (mt = bx*8 + w, bb = by)
        uint4 hi, lo;
        split_pair(st[2 * tid][j16 + gid],         st[2 * tid + 1][j16 + gid],     hi.x, lo.x);
        split_pair(st[2 * tid][j16 + gid + 8],     st[2 * tid + 1][j16 + gid + 8], hi.y, lo.y);
        split_pair(st[2 * tid + 8][j16 + gid],     st[2 * tid + 9][j16 + gid],     hi.z, lo.z);
        split_pair(st[2 * tid + 8][j16 + gid + 8], st[2 * tid + 9][j16 + gid + 8], hi.w, lo.w);
        size_t base = (((size_t)(bx * 8 + w) * KB16_G + by) * 2) * 32 + l;
        g_afg[base] = hi;
        g_afg[base + 32] = lo;
    }
}

// ---------------- softmax over i (one warp per o); iters 1,2 only ----------------
__global__ void softmax_kernel() {
    int o = threadIdx.x >> 5, lane = threadIdx.x & 31;
    float mx = -1e30f;
    for (int i = lane; i < I_CAPS; i += 32) mx = fmaxf(mx, g_b[i * O_CAPS + o]);
    #pragma unroll
    for (int off = 16; off; off >>= 1) mx = fmaxf(mx, __shfl_xor_sync(~0u, mx, off));
    float sum = 0.0f;
    for (int i = lane; i < I_CAPS; i += 32) sum += expf(g_b[i * O_CAPS + o] - mx);
    #pragma unroll
    for (int off = 16; off; off >>= 1) sum += __shfl_xor_sync(~0u, sum, off);
    float inv = 1.0f / sum;
    for (int i = lane; i < I_CAPS; i += 32)
        g_c[i * O_CAPS + o] = expf(g_b[i * O_CAPS + o] - mx) * inv;
}

// ---------------- per-iter: B fragments of (c .* W) ----------------
__global__ void bfrag_kernel(const float* __restrict__ W) {
    int wg = blockIdx.x * 8 + (threadIdx.x >> 5);     // kb*20 + nt
    int l = threadIdx.x & 31;
    int kb = wg / NT_N, nt = wg - kb * NT_N;
    int gid = l >> 2, tid = l & 3;
    int n = nt * 8 + gid, o = n >> 4, p = n & 15;
    int i0 = kb * 2, i1 = kb * 2 + 1;
    float c0 = g_c[i0 * O_CAPS + o], c1 = g_c[i1 * O_CAPS + o];
    const float* w0 = &W[((i0 * O_CAPS + o) * P_SZ + p) * Q_SZ];
    const float* w1 = &W[((i1 * O_CAPS + o) * P_SZ + p) * Q_SZ];
    uint4 r;
    split_pair(c0 * w0[2 * tid], c0 * w0[2 * tid + 1], r.x, r.z);
    split_pair(c1 * w1[2 * tid], c1 * w1[2 * tid + 1], r.y, r.w);
    g_bf[(size_t)wg * 32 + l] = r;
}

// ---------------- per-iter: B fragments of vT ----------------
__global__ void vfrag_kernel() {
    int wg = blockIdx.x * 8 + (threadIdx.x >> 5);     // bb*20 + nt, < 640
    int l = threadIdx.x & 31;
    int bb = wg / NT_N, nt = wg - bb * NT_N;
    int gid = l >> 2, tid = l & 3;
    int n = nt * 8 + gid;
    int b0 = bb * 16 + 2 * tid;
    uint4 r;
    split_pair(g_v[b0 * N_TOT + n],       g_v[(b0 + 1) * N_TOT + n], r.x, r.z);
    split_pair(g_v[(b0 + 8) * N_TOT + n], g_v[(b0 + 9) * N_TOT + n], r.y, r.w);
    g_vf[(size_t)wg * 32 + l] = r;
}

// ---------------- s-GEMM: split-bf16, grid (8, 72); N-split halves acc regs ----------------
__global__ void __launch_bounds__(128) s_gemm_kernel() {
    const int t = threadIdx.x, w = t >> 5, l = t & 31;
    const int gid = l >> 2, tid = l & 3;
    const int mtbase = (blockIdx.x >> 1) * 8 + w * 2;
    const int nh = (blockIdx.x & 1) * NT_H;            // n-half offset in nt units
    const int kb0 = blockIdx.y * 8;
    float* out = &g_spart[blockIdx.y][0];

    float d[2][NT_H][4];
    #pragma unroll
    for (int a = 0; a < 2; a++)
        #pragma unroll
        for (int nt = 0; nt < NT_H; nt++)
            #pragma unroll
            for (int e = 0; e < 4; e++) d[a][nt][e] = 0.0f;

    #pragma unroll 1
    for (int kb = 0; kb < 8; ++kb) {
        size_t a0base = (((size_t)(mtbase + 0) * KB16_S + kb0 + kb) * 2) * 32 + l;
        size_t a1base = (((size_t)(mtbase + 1) * KB16_S + kb0 + kb) * 2) * 32 + l;
        uint4 a0h = g_afs[a0base], a0l = g_afs[a0base + 32];
        uint4 a1h = g_afs[a1base], a1l = g_afs[a1base + 32];
        const uint4* Bk = &g_bf[((size_t)(kb0 + kb) * NT_N + nh) * 32 + l];
        #pragma unroll
        for (int nt = 0; nt < NT_H; nt++) {
            uint4 b = Bk[nt * 32];
            mma_bf16(d[0][nt], a0h.x, a0h.y, a0h.z, a0h.w, b.x, b.y);
            mma_bf16(d[0][nt], a0h.x, a0h.y, a0h.z, a0h.w, b.z, b.w);
            mma_bf16(d[0][nt], a0l.x, a0l.y, a0l.z, a0l.w, b.x, b.y);
            mma_bf16(d[1][nt], a1h.x, a1h.y, a1h.z, a1h.w, b.x, b.y);
            mma_bf16(d[1][nt], a1h.x, a1h.y, a1h.z, a1h.w, b.z, b.w);
            mma_bf16(d[1][nt], a1l.x, a1l.y, a1l.z, a1l.w, b.x, b.y);
        }
    }

    #pragma unroll
    for (int a = 0; a < 2; a++) {
        int m = (mtbase + a) * 16 + gid;
        #pragma unroll
        for (int nt = 0; nt < NT_H; nt++) {
            int col = (nh + nt) * 8 + tid * 2;
            *(float2*)&out[(size_t)m * N_TOT + col] = make_float2(d[a][nt][0], d[a][nt][1]);
            *(float2*)&out[(size_t)(m + 8) * N_TOT + col] = make_float2(d[a][nt][2], d[a][nt][3]);
        }
    }
}

// ---------------- G-GEMM: grid (144, 4); N-split; writes Gpart ----------------
__global__ void __launch_bounds__(128) g_gemm_kernel() {
    const int t = threadIdx.x, w = t >> 5, l = t & 31;
    const int gid = l >> 2, tid = l & 3;
    const int mtbase = (blockIdx.x >> 1) * 8 + w * 2;
    const int nh = (blockIdx.x & 1) * NT_H;
    const int bb0 = blockIdx.y * 8;
    float* out = &g_Gpart[blockIdx.y][0];

    float d[2][NT_H][4];
    #pragma unroll
    for (int a = 0; a < 2; a++)
        #pragma unroll
        for (int nt = 0; nt < NT_H; nt++)
            #pragma unroll
            for (int e = 0; e < 4; e++) d[a][nt][e] = 0.0f;

    #pragma unroll 1
    for (int bb = 0; bb < 8; ++bb) {
        size_t a0base = (((size_t)(mtbase + 0) * KB16_G + bb0 + bb) * 2) * 32 + l;
        size_t a1base = (((size_t)(mtbase + 1) * KB16_G + bb0 + bb) * 2) * 32 + l;
        uint4 a0h = g_afg[a0base], a0l = g_afg[a0base + 32];
        uint4 a1h = g_afg[a1base], a1l = g_afg[a1base + 32];
        const uint4* Bk = &g_vf[((size_t)(bb0 + bb) * NT_N + nh) * 32 + l];
        #pragma unroll
        for (int nt = 0; nt < NT_H; nt++) {
            uint4 b = Bk[nt * 32];
            mma_bf16(d[0][nt], a0h.x, a0h.y, a0h.z, a0h.w, b.x, b.y);
            mma_bf16(d[0][nt], a0h.x, a0h.y, a0h.z, a0h.w, b.z, b.w);
            mma_bf16(d[0][nt], a0l.x, a0l.y, a0l.z, a0l.w, b.x, b.y);
            mma_bf16(d[1][nt], a1h.x, a1h.y, a1h.z, a1h.w, b.x, b.y);
            mma_bf16(d[1][nt], a1h.x, a1h.y, a1h.z, a1h.w, b.z, b.w);
            mma_bf16(d[1][nt], a1l.x, a1l.y, a1l.z, a1l.w, b.x, b.y);
        }
    }

    #pragma unroll
    for (int a = 0; a < 2; a++) {
        int m = (mtbase + a) * 16 + gid;
        #pragma unroll
        for (int nt = 0; nt < NT_H; nt++) {
            int col = (nh + nt) * 8 + tid * 2;
            *(float2*)&out[(size_t)m * N_TOT + col] = make_float2(d[a][nt][0], d[a][nt][1]);
            *(float2*)&out[(size_t)(m + 8) * N_TOT + col] = make_float2(d[a][nt][2], d[a][nt][3]);
        }
    }
}

// ---------------- reduce split-K + squash (float2 vectorized) ----------------
__global__ void squash_kernel(float* __restrict__ out, int write_out) {
    int idx = blockIdx.x * 256 + threadIdx.x;   // pair index < 40960
    int base = idx * 2;
    float2 sv = make_float2(0.0f, 0.0f);
    #pragma unroll 8
    for (int sp = 0; sp < KSPLIT_S; ++sp) {
        float2 p = *(const float2*)&g_spart[sp][base];
        sv.x += p.x; sv.y += p.y;
    }
    float sq = sv.x * sv.x + sv.y * sv.y;
    #pragma unroll
    for (int off = 4; off; off >>= 1)
        sq += __shfl_xor_sync(~0u, sq, off);   // reduce over 8-lane p-group
    float norm = sqrtf(sq + 1e-8f);
    float sc = (sq / (1.0f + sq)) / norm;
    float2 vv = make_float2(sv.x * sc, sv.y * sc);
    *(float2*)&g_v[base] = vv;
    if (write_out) *(float2*)&out[base] = vv;
}

// ---------------- b[i,o] += (1/512) * sum over 8x16 block of Wt .* (sum Gpart) ----------------
__global__ void b_update_kernel() {
    int w = (blockIdx.x * 256 + threadIdx.x) >> 5;
    int lane = threadIdx.x & 31;
    if (w >= I_CAPS * O_CAPS) return;
    int i = w / O_CAPS, o = w - i * O_CAPS;
    int row = i * 8 + (lane >> 2);
    int col = o * 16 + (lane & 3) * 4;
    int base = row * N_TOT + col;
    float4 wv = *(const float4*)&g_Wt[base];
    float4 g0 = *(const float4*)&g_Gpart[0][base];
    float4 g1 = *(const float4*)&g_Gpart[1][base];
    float4 g2 = *(const float4*)&g_Gpart[2][base];
    float4 g3 = *(const float4*)&g_Gpart[3][base];
    float dd = wv.x * (g0.x + g1.x + g2.x + g3.x)
             + wv.y * (g0.y + g1.y + g2.y + g3.y)
             + wv.z * (g0.z + g1.z + g2.z + g3.z)
             + wv.w * (g0.w + g1.w + g2.w + g3.w);
    #pragma unroll
    for (int off = 16; off; off >>= 1) dd += __shfl_xor_sync(~0u, dd, off);
    if (lane == 0) g_b[w] += dd * (1.0f / (float)B_SZ);
}

// ---------------- launch ----------------
extern "C" void kernel_launch(void* const* d_in, const int* in_sizes, int n_in,
                              void* d_out, int out_size) {
    const float* x = (const float*)d_in[0];
    const float* W = (const float*)d_in[1];
    if (n_in >= 2 && in_sizes[0] == I_CAPS * O_CAPS * P_SZ * Q_SZ) {
        W = (const float*)d_in[0];
        x = (const float*)d_in[1];
    }
    float* out = (float*)d_out;

    wt_kernel<<<(K_TOT * N_TOT + 255) / 256, 256>>>(W);      // also uniform c
    xprep_kernel<<<dim3(K_TOT / 128, B_SZ / 16), 256>>>(x);

    for (int it = 0; it < 3; ++it) {
        if (it > 0) softmax_kernel<<<1, 32 * O_CAPS>>>();
        bfrag_kernel<<<(KB16_S * NT_N) / 8, 256>>>(W);
        s_gemm_kernel<<<dim3(MT_S / 4, KSPLIT_S), 128>>>();
        squash_kernel<<<(B_SZ * N_TOT / 2) / 256, 256>>>(out, it == 2 ? 1 : 0);
        if (it < 2) {
            vfrag_kernel<<<(KB16_G * NT_N) / 8, 256>>>();
            g_gemm_kernel<<<dim3(MT_G / 4, BSPLIT_G), 128>>>();
            b_update_kernel<<<(I_CAPS * O_CAPS * 32 + 255) / 256, 256>>>();
        }
    }
}